// round 2
// baseline (speedup 1.0000x reference)
#include <cuda_runtime.h>
#include <cuda_bf16.h>

// ROI-Align (Mask R-CNN multi-level crop_and_resize), POOL=7, C=256, N=1000.
// Inputs (metadata order): boxes[1,1000,4] f32, p2[1,256,256,256], p3[1,256,128,128],
// p4[1,256,64,64], p5[1,256,32,32]. Output: [1000,256,7,7] f32.

#define POOLP 49   // 7*7
#define CCH   256

__global__ __launch_bounds__(256) void roialign_kernel(
    const float* __restrict__ boxes,
    const float* __restrict__ p2,
    const float* __restrict__ p3,
    const float* __restrict__ p4,
    const float* __restrict__ p5,
    float* __restrict__ out)
{
    const int n = blockIdx.x;

    __shared__ int   s_o[4][POOLP];
    __shared__ float s_w[4][POOLP];
    __shared__ const float* s_fm;
    __shared__ int   s_H;
    __shared__ int   s_HW;
    __shared__ float s_box[4];

    if (threadIdx.x == 0) {
        float y1 = boxes[n * 4 + 0];
        float x1 = boxes[n * 4 + 1];
        float y2 = boxes[n * 4 + 2];
        float x2 = boxes[n * 4 + 3];
        float h = y2 - y1;
        float w = x2 - x1;
        // roi_level = clip(round(4 + log2(sqrt(h*w) / (224/1024))), 2, 5)
        // jnp.round is round-half-to-even -> rintf (default RN mode).
        float lvl_f = 4.0f + log2f(sqrtf(h * w) / 0.21875f);
        int lvl = (int)rintf(lvl_f);
        lvl = lvl < 2 ? 2 : (lvl > 5 ? 5 : lvl);

        const float* fm;
        int H;
        if      (lvl == 2) { fm = p2; H = 256; }
        else if (lvl == 3) { fm = p3; H = 128; }
        else if (lvl == 4) { fm = p4; H = 64;  }
        else               { fm = p5; H = 32;  }
        s_fm = fm;
        s_H  = H;
        s_HW = H * H;
        s_box[0] = y1; s_box[1] = x1; s_box[2] = y2; s_box[3] = x2;
    }
    __syncthreads();

    if (threadIdx.x < POOLP) {
        const int py = threadIdx.x / 7;
        const int px = threadIdx.x % 7;
        const int H = s_H;
        const int W = s_H;
        const float y1 = s_box[0], x1 = s_box[1], y2 = s_box[2], x2 = s_box[3];

        // Match jax f32 arithmetic exactly: ty = j / 6.0f (division, not reciprocal-mul)
        float ty = (float)py / 6.0f;
        float tx = (float)px / 6.0f;
        float yy = (y1 + (y2 - y1) * ty) * (float)(H - 1);
        float xx = (x1 + (x2 - x1) * tx) * (float)(W - 1);

        float y0f = floorf(yy);
        float x0f = floorf(xx);
        float wy = yy - y0f;
        float wx = xx - x0f;

        int iy0 = (int)y0f; iy0 = iy0 < 0 ? 0 : (iy0 > H - 1 ? H - 1 : iy0);
        int iy1 = (iy0 + 1 > H - 1) ? (H - 1) : (iy0 + 1);
        int ix0 = (int)x0f; ix0 = ix0 < 0 ? 0 : (ix0 > W - 1 ? W - 1 : ix0);
        int ix1 = (ix0 + 1 > W - 1) ? (W - 1) : (ix0 + 1);

        bool inb = (yy >= 0.0f) && (yy <= (float)(H - 1)) &&
                   (xx >= 0.0f) && (xx <= (float)(W - 1));
        float m = inb ? 1.0f : 0.0f;

        s_o[0][threadIdx.x] = iy0 * W + ix0;
        s_o[1][threadIdx.x] = iy0 * W + ix1;
        s_o[2][threadIdx.x] = iy1 * W + ix0;
        s_o[3][threadIdx.x] = iy1 * W + ix1;
        s_w[0][threadIdx.x] = m * (1.0f - wy) * (1.0f - wx);
        s_w[1][threadIdx.x] = m * (1.0f - wy) * wx;
        s_w[2][threadIdx.x] = m * wy * (1.0f - wx);
        s_w[3][threadIdx.x] = m * wy * wx;
    }
    __syncthreads();

    const float* __restrict__ fm = s_fm;
    const int HW = s_HW;
    float* __restrict__ outn = out + (size_t)n * (CCH * POOLP);

    // 12544 outputs per box, 256 threads -> 49 iterations/thread.
    #pragma unroll 7
    for (int i = threadIdx.x; i < CCH * POOLP; i += 256) {
        int c   = i / POOLP;
        int pos = i - c * POOLP;
        const float* __restrict__ b = fm + c * HW;
        float v = s_w[0][pos] * __ldg(b + s_o[0][pos])
                + s_w[1][pos] * __ldg(b + s_o[1][pos])
                + s_w[2][pos] * __ldg(b + s_o[2][pos])
                + s_w[3][pos] * __ldg(b + s_o[3][pos]);
        outn[i] = v;
    }
}

extern "C" void kernel_launch(void* const* d_in, const int* in_sizes, int n_in,
                              void* d_out, int out_size)
{
    const float* boxes = (const float*)d_in[0];
    const float* p2    = (const float*)d_in[1];
    const float* p3    = (const float*)d_in[2];
    const float* p4    = (const float*)d_in[3];
    const float* p5    = (const float*)d_in[4];
    float* out = (float*)d_out;

    roialign_kernel<<<1000, 256>>>(boxes, p2, p3, p4, p5, out);
}